// round 1
// baseline (speedup 1.0000x reference)
#include <cuda_runtime.h>

#define D_   256
#define SP_  64
#define NB_  128
#define NSL_ 65

// ---------------- device scratch (no allocs allowed) ----------------
__device__ float g_wt[3][NSL_][D_][D_];   // repacked conv weights: [w][slice][i][o]  (51 MB)
__device__ float g_wot[D_*D_];            // wo transposed: [c][o]
__device__ float g_t1[NB_*SP_*D_];        // branch hidden
__device__ float g_qh[NB_*SP_*D_];
__device__ float g_kh[NB_*SP_*D_];
__device__ float g_vh[NB_*SP_*D_];
__device__ float g_att[NB_*SP_*D_];       // attention output, concat layout [b][p][h*32+dk]
__device__ int   g_slice_of_k[225];
__device__ int   g_ps[SP_][40];           // per-p active source pixels
__device__ int   g_pd[SP_][40];           // per-p weight slice ids
__device__ int   g_pcnt[SP_];

// Hollow-mask predicate (derived closed form; 65 kept taps)
__device__ __forceinline__ bool mask_keep(int r, int c) {
    int a = min(r, 14 - r);
    int b = min(c, 14 - c);
    return (a == 7) || (b == 7) || (a >= 5 && b >= 5) || (a == b);
}

// ---------------- setup: slice map, per-p lists, wo transpose ----------------
__global__ void setup_tables(const float* __restrict__ wo) {
    int t = threadIdx.x;
    if (t == 0) {
        int cnt = 0;
        for (int kk = 0; kk < 225; kk++)
            g_slice_of_k[kk] = mask_keep(kk / 15, kk % 15) ? cnt++ : -1;
    }
    __syncthreads();
    if (t < 64) {
        int py = t >> 3, px = t & 7;
        int c = 0;
        for (int s = 0; s < 64; s++) {
            int sy = s >> 3, sx = s & 7;
            int sl = g_slice_of_k[(sy - py + 7) * 15 + (sx - px + 7)];
            if (sl >= 0) { g_ps[t][c] = s; g_pd[t][c] = sl; c++; }
        }
        g_pcnt[t] = c;
    }
    for (int idx = t; idx < D_ * D_; idx += blockDim.x) {
        int o = idx >> 8, cc = idx & 255;
        g_wot[cc * D_ + o] = wo[o * D_ + cc];
    }
}

// ---------------- weight repack: W[o,i,ky,kx] -> g_wt[w][slice][i][o] ----------------
__global__ void wt_prep(const float* __restrict__ wk,
                        const float* __restrict__ wq,
                        const float* __restrict__ wv) {
    const float* src = (blockIdx.y == 0) ? wk : ((blockIdx.y == 1) ? wq : wv);
    int i = blockIdx.x;       // input channel
    int o = threadIdx.x;      // output channel (coalesced writes)
    const float* row = src + ((size_t)o * D_ + i) * 225;
    float* dst = &g_wt[blockIdx.y][0][i][o];
#pragma unroll 1
    for (int kk = 0; kk < 225; kk++) {
        int sl = g_slice_of_k[kk];
        if (sl >= 0) dst[(size_t)sl * (D_ * D_)] = row[kk];
    }
}

__device__ __forceinline__ float* sel_buf(int s) {
    switch (s) {
        case 0: return g_t1;
        case 1: return g_qh;
        case 2: return g_kh;
        case 3: return g_vh;
        default: return g_att;
    }
}

// ---------------- conv as per-p sparse-offset GEMM ----------------
// Block: fixed p, M = 128 (all batches), N = 64 (o tile), K = cnt(p)*256.
// grid = (4 o-tiles, 64 p). 256 threads, 8x4 register micro-tile.
__global__ void __launch_bounds__(256) conv_gemm(const float* __restrict__ Xext, int xsel,
                                                 int widx, const float* __restrict__ bias,
                                                 int ysel, int doRelu) {
    __shared__ float As[8][132];   // [k][m], padded
    __shared__ float Bs[8][68];    // [k][n], padded
    const float* X = Xext ? Xext : sel_buf(xsel);
    float* Y = sel_buf(ysel);

    int p  = blockIdx.y;
    int o0 = blockIdx.x << 6;
    int tid = threadIdx.x;
    int tx = tid & 15, ty = tid >> 4;

    float acc[8][4];
#pragma unroll
    for (int r = 0; r < 8; r++)
#pragma unroll
        for (int c = 0; c < 4; c++) acc[r][c] = 0.f;

    const float* wtbase = &g_wt[widx][0][0][0];
    int cnt = g_pcnt[p];
    int am  = tid >> 1;            // batch row this thread loads
    int akb = (tid & 1) * 4;       // k sub-offset

    for (int n = 0; n < cnt; n++) {
        int s = g_ps[p][n];
        const float* xb = X + (size_t)s * D_ + (size_t)am * (SP_ * D_) + akb;
        const float* wb = wtbase + (size_t)g_pd[p][n] * (D_ * D_) + o0;
#pragma unroll 1
        for (int i0 = 0; i0 < D_; i0 += 8) {
            // A: 128 (batch) x 8 (k), transpose into As[k][m]
            float4 va = *(const float4*)(xb + i0);
            As[akb + 0][am] = va.x; As[akb + 1][am] = va.y;
            As[akb + 2][am] = va.z; As[akb + 3][am] = va.w;
            // B: 8 (k) x 64 (n), coalesced
#pragma unroll
            for (int e = 0; e < 2; e++) {
                int idx = tid + e * 256;
                int kq = idx >> 6, nn = idx & 63;
                Bs[kq][nn] = wb[(size_t)(i0 + kq) * D_ + nn];
            }
            __syncthreads();
#pragma unroll
            for (int kk = 0; kk < 8; kk++) {
                float a[8], b4[4];
                *(float4*)(a)     = *(const float4*)&As[kk][ty * 4];
                *(float4*)(a + 4) = *(const float4*)&As[kk][64 + ty * 4];
                *(float4*)(b4)    = *(const float4*)&Bs[kk][tx * 4];
#pragma unroll
                for (int r = 0; r < 8; r++)
#pragma unroll
                    for (int c = 0; c < 4; c++)
                        acc[r][c] = fmaf(a[r], b4[c], acc[r][c]);
            }
            __syncthreads();
        }
    }
#pragma unroll
    for (int r = 0; r < 8; r++) {
        int m = (r < 4) ? (ty * 4 + r) : (64 + ty * 4 + r - 4);
        float* yrow = Y + (size_t)m * (SP_ * D_) + (size_t)p * D_ + o0;
#pragma unroll
        for (int c = 0; c < 4; c++) {
            int nn = tx * 4 + c;
            float vv = acc[r][c] + bias[o0 + nn];
            if (doRelu) vv = fmaxf(vv, 0.f);
            yrow[nn] = vv;
        }
    }
}

// ---------------- attention: one block per (b,h) ----------------
__global__ void __launch_bounds__(256) attn_kernel() {
    __shared__ float sq[64][33];
    __shared__ float sk[64][33];
    __shared__ float sv[64][33];
    __shared__ float sc[64][64];
    int b = blockIdx.x >> 3, h = blockIdx.x & 7;
    int tid = threadIdx.x;
    const float* qb = g_qh + (size_t)b * (SP_ * D_) + h * 32;
    const float* kb = g_kh + (size_t)b * (SP_ * D_) + h * 32;
    const float* vb = g_vh + (size_t)b * (SP_ * D_) + h * 32;
#pragma unroll
    for (int e = 0; e < 8; e++) {
        int idx = tid + e * 256;
        int pp = idx >> 5, dk = idx & 31;
        sq[pp][dk] = qb[pp * D_ + dk];
        sk[pp][dk] = kb[pp * D_ + dk];
        sv[pp][dk] = vb[pp * D_ + dk];
    }
    __syncthreads();
    int lane = tid & 31, w = tid >> 5;
    const float scale = 0.17677669529663687f;   // 1/sqrt(32)
#pragma unroll 1
    for (int r = 0; r < 8; r++) {
        int i = w * 8 + r;
        float a0 = 0.f, a1 = 0.f;
#pragma unroll
        for (int dk = 0; dk < 32; dk++) {
            float qv = sq[i][dk];
            a0 = fmaf(qv, sk[lane][dk], a0);
            a1 = fmaf(qv, sk[lane + 32][dk], a1);
        }
        a0 *= scale; a1 *= scale;
        float mx = fmaxf(a0, a1);
#pragma unroll
        for (int off = 16; off; off >>= 1) mx = fmaxf(mx, __shfl_xor_sync(0xffffffffu, mx, off));
        float e0 = __expf(a0 - mx), e1 = __expf(a1 - mx);
        float sm = e0 + e1;
#pragma unroll
        for (int off = 16; off; off >>= 1) sm += __shfl_xor_sync(0xffffffffu, sm, off);
        float inv = 1.0f / sm;
        sc[i][lane] = e0 * inv;
        sc[i][lane + 32] = e1 * inv;
    }
    __syncthreads();
    float o[8];
#pragma unroll
    for (int r = 0; r < 8; r++) o[r] = 0.f;
#pragma unroll 1
    for (int j = 0; j < 64; j++) {
        float vv = sv[j][lane];
#pragma unroll
        for (int r = 0; r < 8; r++) o[r] = fmaf(sc[w * 8 + r][j], vv, o[r]);
    }
    float* ob = g_att + (size_t)b * (SP_ * D_) + h * 32 + lane;
#pragma unroll
    for (int r = 0; r < 8; r++) ob[(size_t)(w * 8 + r) * D_] = o[r];
}

// ---------------- output projection: [8192,256] @ wot[256,256] + bo ----------------
__global__ void __launch_bounds__(256) out_gemm(const float* __restrict__ bo, float* __restrict__ Y) {
    __shared__ float As[8][132];
    __shared__ float Bs[8][68];
    int o0   = blockIdx.x << 6;
    int row0 = blockIdx.y << 7;
    int tid = threadIdx.x;
    int tx = tid & 15, ty = tid >> 4;
    float acc[8][4];
#pragma unroll
    for (int r = 0; r < 8; r++)
#pragma unroll
        for (int c = 0; c < 4; c++) acc[r][c] = 0.f;
    int am = tid >> 1, akb = (tid & 1) * 4;
    const float* A = g_att + (size_t)(row0 + am) * D_ + akb;
#pragma unroll 1
    for (int i0 = 0; i0 < D_; i0 += 8) {
        float4 va = *(const float4*)(A + i0);
        As[akb + 0][am] = va.x; As[akb + 1][am] = va.y;
        As[akb + 2][am] = va.z; As[akb + 3][am] = va.w;
#pragma unroll
        for (int e = 0; e < 2; e++) {
            int idx = tid + e * 256;
            int kq = idx >> 6, nn = idx & 63;
            Bs[kq][nn] = g_wot[(size_t)(i0 + kq) * D_ + o0 + nn];
        }
        __syncthreads();
#pragma unroll
        for (int kk = 0; kk < 8; kk++) {
            float a[8], b4[4];
            *(float4*)(a)     = *(const float4*)&As[kk][ty * 4];
            *(float4*)(a + 4) = *(const float4*)&As[kk][64 + ty * 4];
            *(float4*)(b4)    = *(const float4*)&Bs[kk][tx * 4];
#pragma unroll
            for (int r = 0; r < 8; r++)
#pragma unroll
                for (int c = 0; c < 4; c++)
                    acc[r][c] = fmaf(a[r], b4[c], acc[r][c]);
        }
        __syncthreads();
    }
#pragma unroll
    for (int r = 0; r < 8; r++) {
        int m = (r < 4) ? (ty * 4 + r) : (64 + ty * 4 + r - 4);
        float* yrow = Y + (size_t)(row0 + m) * D_ + o0;
#pragma unroll
        for (int c = 0; c < 4; c++) {
            int nn = tx * 4 + c;
            yrow[nn] = acc[r][c] + bo[o0 + nn];
        }
    }
}

// ---------------- launch ----------------
extern "C" void kernel_launch(void* const* d_in, const int* in_sizes, int n_in,
                              void* d_out, int out_size) {
    (void)in_sizes; (void)n_in; (void)out_size;
    const float* q  = (const float*)d_in[0];
    const float* k  = (const float*)d_in[1];
    const float* v  = (const float*)d_in[2];
    const float* wk = (const float*)d_in[3];
    const float* bk = (const float*)d_in[4];
    const float* wq = (const float*)d_in[5];
    const float* bq = (const float*)d_in[6];
    const float* wv = (const float*)d_in[7];
    const float* bv = (const float*)d_in[8];
    const float* wo = (const float*)d_in[9];
    const float* bo = (const float*)d_in[10];
    float* out = (float*)d_out;

    setup_tables<<<1, 256>>>(wo);
    wt_prep<<<dim3(256, 3), 256>>>(wk, wq, wv);

    dim3 cgrid(4, 64);
    // k branch: relu(conv(k, wk)+bk) -> t1 ; conv(t1, wk)+bk -> kh
    conv_gemm<<<cgrid, 256>>>(k, -1, 0, bk, 0, 1);
    conv_gemm<<<cgrid, 256>>>(nullptr, 0, 0, bk, 2, 0);
    // q branch: relu(conv(q, wq)+bq) -> t1 ; conv(t1, wk)+bk -> qh   (weight-sharing quirk)
    conv_gemm<<<cgrid, 256>>>(q, -1, 1, bq, 0, 1);
    conv_gemm<<<cgrid, 256>>>(nullptr, 0, 0, bk, 1, 0);
    // v branch: relu(conv(v, wv)+bv) -> t1 ; conv(t1, wv)+bv -> vh
    conv_gemm<<<cgrid, 256>>>(v, -1, 2, bv, 0, 1);
    conv_gemm<<<cgrid, 256>>>(nullptr, 0, 2, bv, 3, 0);

    attn_kernel<<<NB_ * 8, 256>>>();
    out_gemm<<<dim3(4, 64), 256>>>(bo, out);
}

// round 3
// speedup vs baseline: 4.7260x; 4.7260x over previous
#include <cuda_runtime.h>
#include <cstdint>

#define D_   256
#define SP_  64
#define NB_  128
#define NSL_ 65

// ---------------- device scratch ----------------
__device__ float g_wt[3][NSL_][D_][D_];   // [w][slice][i][o]  (B: rows k=i, cols n=o)
__device__ float g_wot[D_ * D_];
__device__ float g_t1[NB_ * SP_ * D_];
__device__ float g_t2[NB_ * SP_ * D_];
__device__ float g_t3[NB_ * SP_ * D_];
__device__ float g_qh[NB_ * SP_ * D_];
__device__ float g_kh[NB_ * SP_ * D_];
__device__ float g_vh[NB_ * SP_ * D_];
__device__ float g_att[NB_ * SP_ * D_];
__device__ int   g_slice_of_k[225];
__device__ int   g_ps[SP_][40];
__device__ int   g_pd[SP_][40];
__device__ int   g_pcnt[SP_];

__device__ __forceinline__ bool mask_keep(int r, int c) {
    int a = min(r, 14 - r);
    int b = min(c, 14 - c);
    return (a == 7) || (b == 7) || (a >= 5 && b >= 5) || (a == b);
}

__device__ __forceinline__ float* sel_buf(int s) {
    switch (s) {
        case 0: return g_t1;
        case 1: return g_t2;
        case 2: return g_t3;
        case 3: return g_qh;
        case 4: return g_kh;
        case 5: return g_vh;
        default: return g_att;
    }
}

// ---------------- small PTX helpers (sm_80+ features only) ----------------
__device__ __forceinline__ uint32_t smem_u32(const void* p) {
    uint32_t a;
    asm("{ .reg .u64 t; cvta.to.shared.u64 t, %1; cvt.u32.u64 %0, t; }" : "=r"(a) : "l"(p));
    return a;
}
__device__ __forceinline__ void cp16(uint32_t dst, const void* src) {
    asm volatile("cp.async.cg.shared.global [%0], [%1], 16;" :: "r"(dst), "l"(src));
}
__device__ __forceinline__ void cp_commit() {
    asm volatile("cp.async.commit_group;" ::: "memory");
}
template <int N>
__device__ __forceinline__ void cp_wait() {
    asm volatile("cp.async.wait_group %0;" :: "n"(N) : "memory");
}
__device__ __forceinline__ uint32_t f2tf32(float x) {
    uint32_t r;
    asm("cvt.rna.tf32.f32 %0, %1;" : "=r"(r) : "f"(x));
    return r;
}
__device__ __forceinline__ void mma_tf32(float& c0, float& c1, float& c2, float& c3,
                                         uint32_t a0, uint32_t a1, uint32_t a2, uint32_t a3,
                                         uint32_t b0, uint32_t b1) {
    asm volatile(
        "mma.sync.aligned.m16n8k8.row.col.f32.tf32.tf32.f32 "
        "{%0,%1,%2,%3}, {%4,%5,%6,%7}, {%8,%9}, {%0,%1,%2,%3};"
        : "+f"(c0), "+f"(c1), "+f"(c2), "+f"(c3)
        : "r"(a0), "r"(a1), "r"(a2), "r"(a3), "r"(b0), "r"(b1));
}

// ---------------- setup ----------------
__global__ void setup_tables(const float* __restrict__ wo) {
    int t = threadIdx.x;
    if (t == 0) {
        int cnt = 0;
        for (int kk = 0; kk < 225; kk++)
            g_slice_of_k[kk] = mask_keep(kk / 15, kk % 15) ? cnt++ : -1;
    }
    __syncthreads();
    if (t < 64) {
        int py = t >> 3, px = t & 7;
        int c = 0;
        for (int s = 0; s < 64; s++) {
            int sy = s >> 3, sx = s & 7;
            int sl = g_slice_of_k[(sy - py + 7) * 15 + (sx - px + 7)];
            if (sl >= 0) { g_ps[t][c] = s; g_pd[t][c] = sl; c++; }
        }
        g_pcnt[t] = c;
    }
    for (int idx = t; idx < D_ * D_; idx += blockDim.x) {
        int o = idx >> 8, cc = idx & 255;
        g_wot[cc * D_ + o] = wo[o * D_ + cc];
    }
}

// weight repack: linear coalesced f4 reads, scattered useful writes.
// src layout [o][i][kk] (kk=225), dst g_wt[w][slice][i][o].
__global__ void wt_prep(const float* __restrict__ wk,
                        const float* __restrict__ wq,
                        const float* __restrict__ wv) {
    int w = blockIdx.y;
    const float* src = (w == 0) ? wk : ((w == 1) ? wq : wv);
    size_t base = ((size_t)blockIdx.x * 256 + threadIdx.x) * 4;
    float4 v = *(const float4*)(src + base);
    float vv[4] = {v.x, v.y, v.z, v.w};
#pragma unroll
    for (int e = 0; e < 4; e++) {
        size_t idx = base + e;
        int kk = (int)(idx % 225);
        int oi = (int)(idx / 225);
        int i = oi & 255, o = oi >> 8;
        int sl = g_slice_of_k[kk];
        if (sl >= 0) g_wt[w][sl][i][o] = vv[e];
    }
}

// ---------------- conv as tf32 mma.sync GEMM ----------------
// grid = (2 n-tiles, 64 p, 3 branches). CTA: M=128 (batch) x N=128 (o-tile),
// K = cnt(p)*256 streamed in k=32 chunks, cp.async double-buffered.
#define AS_STRIDE 36
#define BS_STRIDE 136
#define A_STG (128 * AS_STRIDE)               /* floats */
#define B_STG (32 * BS_STRIDE)
#define SMEM_FLOATS (2 * A_STG + 2 * B_STG)
#define SMEM_BYTES (SMEM_FLOATS * 4)          /* 71680 B */

__global__ void __launch_bounds__(256, 1) conv_mma(
    const float* xa, const float* xb, const float* xc,
    int xsa, int xsb, int xsc,
    int wa, int wb, int wc,
    const float* ba, const float* bb, const float* bc,
    int ya, int yb, int yc, int doRelu)
{
    extern __shared__ float smem[];
    float* As = smem;                    // [2][128][36]
    float* Bs = smem + 2 * A_STG;        // [2][32][136]

    int tid = threadIdx.x, wid = tid >> 5, lane = tid & 31;
    int o0 = blockIdx.x << 7;
    int p  = blockIdx.y;
    int br = blockIdx.z;

    const float* X; int widx; const float* bias; int ysel;
    if (br == 0)      { X = xa ? xa : sel_buf(xsa); widx = wa; bias = ba; ysel = ya; }
    else if (br == 1) { X = xb ? xb : sel_buf(xsb); widx = wb; bias = bb; ysel = yb; }
    else              { X = xc ? xc : sel_buf(xsc); widx = wc; bias = bc; ysel = yc; }
    float* Y = sel_buf(ysel);
    const float* WT = &g_wt[widx][0][0][0];

    int cnt = g_pcnt[p];
    int NC  = cnt * 8;

    // load-thread mapping
    int arow = tid >> 1;                 // A: 2 threads per batch row (8 f4 per row)
    int ac4  = (tid & 1) * 4;
    int brow = tid >> 5;                 // B: but we use idx-based mapping below
    (void)brow;

    uint32_t as_base = smem_u32(As);
    uint32_t bs_base = smem_u32(Bs);

    // warp tiling: 2 (m) x 4 (n)
    int wm = wid & 1, wn = wid >> 1;
    int g = lane >> 2, t = lane & 3;

    float acc[4][4][4];
#pragma unroll
    for (int mi = 0; mi < 4; mi++)
#pragma unroll
        for (int ni = 0; ni < 4; ni++)
#pragma unroll
            for (int e = 0; e < 4; e++) acc[mi][ni][e] = 0.f;

    // stage issuer
    auto issue = [&](int n) {
        int buf = n & 1;
        int si = n >> 3;
        int s  = g_ps[p][si];
        int sl = g_pd[p][si];
        int i0 = (n & 7) * 32;
        // A: 128 rows x 32 k -> As[buf][m][k]; thread handles 4 f4
        const float* asrc = X + ((size_t)(arow * SP_ + s) * D_ + i0);
        uint32_t adst = as_base + (uint32_t)(buf * A_STG + arow * AS_STRIDE) * 4;
#pragma unroll
        for (int j = 0; j < 4; j++)
            cp16(adst + (uint32_t)(ac4 + j) * 16, asrc + (ac4 + j) * 4);
        // B: 32 rows(k=i) x 128 (n=o) -> Bs[buf][k][n]; idx = tid + 256*j
        const float* wbase = WT + (size_t)sl * (D_ * D_) + (size_t)i0 * D_ + o0;
#pragma unroll
        for (int j = 0; j < 4; j++) {
            int idx = tid + (j << 8);
            int r = idx >> 5, c4 = idx & 31;
            cp16(bs_base + (uint32_t)(buf * B_STG + r * BS_STRIDE + c4 * 4) * 4,
                 wbase + (size_t)r * D_ + c4 * 4);
        }
    };

    issue(0);
    cp_commit();

#pragma unroll 1
    for (int n = 0; n < NC; n++) {
        if (n + 1 < NC) {
            issue(n + 1);
            cp_commit();
            cp_wait<1>();
        } else {
            cp_wait<0>();
        }
        __syncthreads();

        const float* Ab = As + (n & 1) * A_STG;
        const float* Bb = Bs + (n & 1) * B_STG;
#pragma unroll
        for (int kk = 0; kk < 4; kk++) {
            int k0 = kk * 8;
            uint32_t af[4][4];
#pragma unroll
            for (int mi = 0; mi < 4; mi++) {
                int m = wm * 64 + mi * 16;
                const float* ap = Ab + (size_t)(m + g) * AS_STRIDE + k0 + t;
                af[mi][0] = f2tf32(ap[0]);
                af[mi][1] = f2tf32(ap[8 * AS_STRIDE]);
                af[mi][2] = f2tf32(ap[4]);
                af[mi][3] = f2tf32(ap[8 * AS_STRIDE + 4]);
            }
            uint32_t bf[4][2];
#pragma unroll
            for (int ni = 0; ni < 4; ni++) {
                int nn = wn * 32 + ni * 8;
                const float* bp = Bb + (size_t)(k0 + t) * BS_STRIDE + nn + g;
                bf[ni][0] = f2tf32(bp[0]);
                bf[ni][1] = f2tf32(bp[4 * BS_STRIDE]);
            }
#pragma unroll
            for (int mi = 0; mi < 4; mi++)
#pragma unroll
                for (int ni = 0; ni < 4; ni++)
                    mma_tf32(acc[mi][ni][0], acc[mi][ni][1], acc[mi][ni][2], acc[mi][ni][3],
                             af[mi][0], af[mi][1], af[mi][2], af[mi][3],
                             bf[ni][0], bf[ni][1]);
        }
        __syncthreads();
    }

    // epilogue: c0=(g, 2t) c1=(g, 2t+1) c2=(g+8, 2t) c3=(g+8, 2t+1)
#pragma unroll
    for (int mi = 0; mi < 4; mi++) {
#pragma unroll
        for (int ni = 0; ni < 4; ni++) {
            int m  = wm * 64 + mi * 16 + g;
            int nn = o0 + wn * 32 + ni * 8 + 2 * t;
            float b0 = bias[nn], b1 = bias[nn + 1];
            float v0 = acc[mi][ni][0] + b0, v1 = acc[mi][ni][1] + b1;
            float v2 = acc[mi][ni][2] + b0, v3 = acc[mi][ni][3] + b1;
            if (doRelu) {
                v0 = fmaxf(v0, 0.f); v1 = fmaxf(v1, 0.f);
                v2 = fmaxf(v2, 0.f); v3 = fmaxf(v3, 0.f);
            }
            float* y0 = Y + ((size_t)(m * SP_ + p) * D_ + nn);
            float* y1 = Y + ((size_t)((m + 8) * SP_ + p) * D_ + nn);
            *(float2*)y0 = make_float2(v0, v1);
            *(float2*)y1 = make_float2(v2, v3);
        }
    }
}

// ---------------- attention ----------------
__global__ void __launch_bounds__(256) attn_kernel() {
    __shared__ float sq[64][33];
    __shared__ float sk[64][33];
    __shared__ float sv[64][33];
    __shared__ float sc[64][64];
    int b = blockIdx.x >> 3, h = blockIdx.x & 7;
    int tid = threadIdx.x;
    const float* qb = g_qh + (size_t)b * (SP_ * D_) + h * 32;
    const float* kb = g_kh + (size_t)b * (SP_ * D_) + h * 32;
    const float* vb = g_vh + (size_t)b * (SP_ * D_) + h * 32;
#pragma unroll
    for (int e = 0; e < 8; e++) {
        int idx = tid + e * 256;
        int pp = idx >> 5, dk = idx & 31;
        sq[pp][dk] = qb[pp * D_ + dk];
        sk[pp][dk] = kb[pp * D_ + dk];
        sv[pp][dk] = vb[pp * D_ + dk];
    }
    __syncthreads();
    int lane = tid & 31, w = tid >> 5;
    const float scale = 0.17677669529663687f;
#pragma unroll 1
    for (int r = 0; r < 8; r++) {
        int i = w * 8 + r;
        float a0 = 0.f, a1 = 0.f;
#pragma unroll
        for (int dk = 0; dk < 32; dk++) {
            float qv = sq[i][dk];
            a0 = fmaf(qv, sk[lane][dk], a0);
            a1 = fmaf(qv, sk[lane + 32][dk], a1);
        }
        a0 *= scale; a1 *= scale;
        float mx = fmaxf(a0, a1);
#pragma unroll
        for (int off = 16; off; off >>= 1) mx = fmaxf(mx, __shfl_xor_sync(0xffffffffu, mx, off));
        float e0 = __expf(a0 - mx), e1 = __expf(a1 - mx);
        float sm = e0 + e1;
#pragma unroll
        for (int off = 16; off; off >>= 1) sm += __shfl_xor_sync(0xffffffffu, sm, off);
        float inv = 1.0f / sm;
        sc[i][lane] = e0 * inv;
        sc[i][lane + 32] = e1 * inv;
    }
    __syncthreads();
    float o[8];
#pragma unroll
    for (int r = 0; r < 8; r++) o[r] = 0.f;
#pragma unroll 1
    for (int j = 0; j < 64; j++) {
        float vv = sv[j][lane];
#pragma unroll
        for (int r = 0; r < 8; r++) o[r] = fmaf(sc[w * 8 + r][j], vv, o[r]);
    }
    float* ob = g_att + (size_t)b * (SP_ * D_) + h * 32 + lane;
#pragma unroll
    for (int r = 0; r < 8; r++) ob[(size_t)(w * 8 + r) * D_] = o[r];
}

// ---------------- output projection ----------------
__global__ void __launch_bounds__(256) out_gemm(const float* __restrict__ bo, float* __restrict__ Y) {
    __shared__ float As2[8][132];
    __shared__ float Bs2[8][68];
    int o0   = blockIdx.x << 6;
    int row0 = blockIdx.y << 7;
    int tid = threadIdx.x;
    int tx = tid & 15, ty = tid >> 4;
    float acc[8][4];
#pragma unroll
    for (int r = 0; r < 8; r++)
#pragma unroll
        for (int c = 0; c < 4; c++) acc[r][c] = 0.f;
    int am = tid >> 1, akb = (tid & 1) * 4;
    const float* A = g_att + (size_t)(row0 + am) * D_ + akb;
#pragma unroll 1
    for (int i0 = 0; i0 < D_; i0 += 8) {
        float4 va = *(const float4*)(A + i0);
        As2[akb + 0][am] = va.x; As2[akb + 1][am] = va.y;
        As2[akb + 2][am] = va.z; As2[akb + 3][am] = va.w;
#pragma unroll
        for (int e = 0; e < 2; e++) {
            int idx = tid + e * 256;
            int kq = idx >> 6, nn = idx & 63;
            Bs2[kq][nn] = g_wot[(size_t)(i0 + kq) * D_ + o0 + nn];
        }
        __syncthreads();
#pragma unroll
        for (int kk = 0; kk < 8; kk++) {
            float a[8], b4[4];
            *(float4*)(a)     = *(const float4*)&As2[kk][ty * 4];
            *(float4*)(a + 4) = *(const float4*)&As2[kk][64 + ty * 4];
            *(float4*)(b4)    = *(const float4*)&Bs2[kk][tx * 4];
#pragma unroll
            for (int r = 0; r < 8; r++)
#pragma unroll
                for (int c = 0; c < 4; c++)
                    acc[r][c] = fmaf(a[r], b4[c], acc[r][c]);
        }
        __syncthreads();
    }
#pragma unroll
    for (int r = 0; r < 8; r++) {
        int m = (r < 4) ? (ty * 4 + r) : (64 + ty * 4 + r - 4);
        float* yrow = Y + (size_t)(row0 + m) * D_ + o0;
#pragma unroll
        for (int c = 0; c < 4; c++) {
            int nn = tx * 4 + c;
            yrow[nn] = acc[r][c] + bo[o0 + nn];
        }
    }
}

// ---------------- launch ----------------
extern "C" void kernel_launch(void* const* d_in, const int* in_sizes, int n_in,
                              void* d_out, int out_size) {
    (void)in_sizes; (void)n_in; (void)out_size;
    const float* q  = (const float*)d_in[0];
    const float* k  = (const float*)d_in[1];
    const float* v  = (const float*)d_in[2];
    const float* wk = (const float*)d_in[3];
    const float* bk = (const float*)d_in[4];
    const float* wq = (const float*)d_in[5];
    const float* bq = (const float*)d_in[6];
    const float* wv = (const float*)d_in[7];
    const float* bv = (const float*)d_in[8];
    const float* wo = (const float*)d_in[9];
    const float* bo = (const float*)d_in[10];
    float* out = (float*)d_out;

    static int smem_set = 0;
    if (!smem_set) {
        cudaFuncSetAttribute(conv_mma, cudaFuncAttributeMaxDynamicSharedMemorySize, SMEM_BYTES);
        smem_set = 1;
    }

    setup_tables<<<1, 256>>>(wo);
    wt_prep<<<dim3(14400, 3), 256>>>(wk, wq, wv);

    dim3 cgrid(2, 64, 3);
    // Phase 1: t1=relu(conv(k,wk)+bk), t2=relu(conv(q,wq)+bq), t3=relu(conv(v,wv)+bv)
    conv_mma<<<cgrid, 256, SMEM_BYTES>>>(k, q, v,
                                         -1, -1, -1,
                                         0, 1, 2,
                                         bk, bq, bv,
                                         0, 1, 2, 1);
    // Phase 2: kh=conv(t1,wk)+bk, qh=conv(t2,wk)+bk (weight-sharing quirk), vh=conv(t3,wv)+bv
    conv_mma<<<cgrid, 256, SMEM_BYTES>>>(nullptr, nullptr, nullptr,
                                         0, 1, 2,
                                         0, 0, 2,
                                         bk, bk, bv,
                                         4, 3, 5, 0);

    attn_kernel<<<NB_ * 8, 256>>>();
    out_gemm<<<dim3(4, 64), 256>>>(bo, out);
}